// round 7
// baseline (speedup 1.0000x reference)
#include <cuda_runtime.h>
#include <cstdint>

#define T_SEQ 2048
#define NB    64
#define DIN   256
#define NH    256

// scratch: precomputed input projection xw[t][b][h]  (128 MB, static — no allocs)
__device__ float g_xw[(size_t)T_SEQ * NB * NH];

// padded h index: +4 floats of pad per 16-float window (bank de-conflict)
#define PHYS16(k) ((k) + (((k) >> 4) << 2))
#define HPAD2 320   // 256 + 16 windows * 4 pad

// ---------------- packed fp32x2 helpers (sm_100+) ----------------
__device__ __forceinline__ unsigned long long fma2(unsigned long long a,
                                                   unsigned long long b,
                                                   unsigned long long c) {
    unsigned long long d;
    asm("fma.rn.f32x2 %0, %1, %2, %3;" : "=l"(d) : "l"(a), "l"(b), "l"(c));
    return d;
}
__device__ __forceinline__ float f2sum(unsigned long long v) {
    float lo, hi;
    asm("mov.b64 {%0, %1}, %2;" : "=f"(lo), "=f"(hi) : "l"(v));
    return lo + hi;
}
__device__ __forceinline__ unsigned long long packf2(float lo, float hi) {
    unsigned long long r;
    asm("mov.b64 %0, {%1, %2};" : "=l"(r) : "f"(lo), "f"(hi));
    return r;
}
__device__ __forceinline__ uint32_t smem_u32(const void* p) {
    uint32_t a;
    asm("{ .reg .u64 t; cvta.to.shared.u64 t, %1; cvt.u32.u64 %0, t; }"
        : "=r"(a) : "l"(p));
    return a;
}
__device__ __forceinline__ uint32_t mapa_(uint32_t addr, int rank) {
    uint32_t r;
    asm("mapa.shared::cluster.u32 %0, %1, %2;" : "=r"(r) : "r"(addr), "r"(rank));
    return r;
}
__device__ __forceinline__ void cluster_sync_() {
    asm volatile("barrier.cluster.arrive.aligned;\n\t"
                 "barrier.cluster.wait.aligned;" ::: "memory");
}
__device__ __forceinline__ void cluster_arrive_() {
    asm volatile("barrier.cluster.arrive.aligned;" ::: "memory");
}
__device__ __forceinline__ void cluster_wait_() {
    asm volatile("barrier.cluster.wait.aligned;" ::: "memory");
}
__device__ __forceinline__ void st_cluster_b64(uint32_t addr, unsigned long long v) {
    asm volatile("st.shared::cluster.b64 [%0], %1;" :: "r"(addr), "l"(v) : "memory");
}
__device__ __forceinline__ float tanh_fast(float x) {
    float e = __expf(2.0f * x);
    return 1.0f - __fdividef(2.0f, e + 1.0f);
}

// =================================================================
// Kernel 1: input projection  (unchanged — proven)
// =================================================================
__global__ void __launch_bounds__(256, 1)
xw_kernel(const float* __restrict__ x,
          const float* __restrict__ w_ih,
          const float* __restrict__ b_ih,
          const float* __restrict__ b_hh) {
    __shared__ __align__(16) float xs[8][256];
    __shared__ float pbuf[8 * 512];

    const int tid  = threadIdx.x;
    const int w    = tid >> 5;
    const int lane = tid & 31;
    const int kg   = w >> 1;
    const int og   = ((w & 1) << 5) | lane;
    const int half = blockIdx.y;
    const int rowbase0 = blockIdx.x * 128;

    unsigned long long wa[32], wb[32];
    {
        const int j0 = half * 128 + og, j1 = j0 + 64;
        const unsigned long long* p0 =
            (const unsigned long long*)(w_ih + (size_t)j0 * DIN + kg * 64);
        const unsigned long long* p1 =
            (const unsigned long long*)(w_ih + (size_t)j1 * DIN + kg * 64);
#pragma unroll
        for (int i = 0; i < 32; i++) { wa[i] = p0[i]; wb[i] = p1[i]; }
    }
    float bias = 0.f;
    if (tid < 128) bias = b_ih[half * 128 + tid] + b_hh[half * 128 + tid];

    const float4* xg = (const float4*)x;
    {
        int q = tid, r = q >> 6, c4 = q & 63;
        ((float4*)xs)[q]       = xg[(size_t)(rowbase0 + r) * 64 + c4];
        ((float4*)xs)[q + 256] = xg[(size_t)(rowbase0 + 4 + r) * 64 + c4];
    }
    __syncthreads();

    for (int it = 0; it < 16; it++) {
        const int rowbase = rowbase0 + it * 8;
        float4 n0, n1;
        if (it < 15) {
            int q = tid, r = q >> 6, c4 = q & 63;
            int nrb = rowbase + 8;
            n0 = xg[(size_t)(nrb + r) * 64 + c4];
            n1 = xg[(size_t)(nrb + 4 + r) * 64 + c4];
        }
        unsigned long long acc[8][2];
#pragma unroll
        for (int r = 0; r < 8; r++) { acc[r][0] = 0ull; acc[r][1] = 0ull; }
#pragma unroll
        for (int r = 0; r < 8; r++) {
            const ulonglong2* xp = (const ulonglong2*)&xs[r][kg * 64];
#pragma unroll
            for (int i = 0; i < 16; i++) {
                ulonglong2 hv = xp[i];
                acc[r][0] = fma2(wa[2 * i],     hv.x, acc[r][0]);
                acc[r][0] = fma2(wa[2 * i + 1], hv.y, acc[r][0]);
                acc[r][1] = fma2(wb[2 * i],     hv.x, acc[r][1]);
                acc[r][1] = fma2(wb[2 * i + 1], hv.y, acc[r][1]);
            }
        }
#pragma unroll
        for (int r = 0; r < 8; r++) {
            pbuf[r * 512 + kg * 128 + og]      = f2sum(acc[r][0]);
            pbuf[r * 512 + kg * 128 + og + 64] = f2sum(acc[r][1]);
        }
        __syncthreads();
        if (it < 15) {
            int q = tid;
            ((float4*)xs)[q]       = n0;
            ((float4*)xs)[q + 256] = n1;
        }
        if (tid < 128) {
#pragma unroll
            for (int r = 0; r < 8; r++) {
                float s = pbuf[r * 512 + tid] + pbuf[r * 512 + 128 + tid] +
                          pbuf[r * 512 + 256 + tid] + pbuf[r * 512 + 384 + tid] + bias;
                g_xw[(size_t)(rowbase + r) * NH + half * 128 + tid] = s;
            }
        }
        __syncthreads();
    }
}

// =================================================================
// Kernel 2: recurrence v7 — R5 skeleton, 2 chains per cluster.
//   32 clusters x 2 CTAs x 256 thr. Cluster handles batch rows 2*cid, 2*cid+1.
//   One barrier round-trip per superstep serves BOTH chains (weights shared).
//   Per superstep: localFMA(A,B) -> wait -> remoteFMA(A,B) -> reduce ->
//   tanh/store/push(A,B) -> arrive -> STG + xw prefetch -> __syncthreads.
// =================================================================
__global__ void __launch_bounds__(256, 1) __cluster_dims__(2, 1, 1)
rnn_kernel(const float* __restrict__ w_hh, float* __restrict__ out) {
    __shared__ __align__(16) float hbuf[2][2][HPAD2];  // [chain][buf][...]

    const int tid  = threadIdx.x;
    const int w    = tid >> 5, l = tid & 31;
    const int cg   = l & 3,  kp = l >> 2;
    const int cid  = blockIdx.x >> 1;
    const int c    = blockIdx.x & 1;
    const int peer = c ^ 1;
    const int b0   = 2 * cid, b1 = 2 * cid + 1;
    const int j0   = c * 128 + w * 16 + cg * 4;   // 4 output cols
    const int lk   = c    * 128 + kp * 16;        // local  16-k window
    const int rk   = peer * 128 + kp * 16;        // remote 16-k window
    const bool writer = (kp == 0);

    // register-resident weights (shared by both chains): 4 cols x 32 k
    unsigned long long wl[4][8], wr[4][8];
#pragma unroll
    for (int cc = 0; cc < 4; cc++) {
        const float* row = w_hh + (size_t)(j0 + cc) * NH;
        const unsigned long long* pl = (const unsigned long long*)(row + lk);
        const unsigned long long* pr = (const unsigned long long*)(row + rk);
#pragma unroll
        for (int i = 0; i < 8; i++) { wl[cc][i] = pl[i]; wr[cc][i] = pr[i]; }
    }

    for (int i = tid; i < 2 * 2 * HPAD2; i += 256) ((float*)hbuf)[i] = 0.f;

    const int pj = PHYS16(j0);
    const uint32_t rdA[2] = { mapa_(smem_u32(&hbuf[0][0][pj]), peer),
                              mapa_(smem_u32(&hbuf[0][1][pj]), peer) };
    const uint32_t rdB[2] = { mapa_(smem_u32(&hbuf[1][0][pj]), peer),
                              mapa_(smem_u32(&hbuf[1][1][pj]), peer) };

    cluster_sync_();                              // zeros visible cluster-wide

    float4 xcA, x1A, x2A, xcB, x1B, x2B;
    if (writer) {
        xcA = *(const float4*)&g_xw[(size_t)b0 * NH + j0];
        x1A = *(const float4*)&g_xw[((size_t)NB + b0) * NH + j0];
        xcB = *(const float4*)&g_xw[(size_t)b1 * NH + j0];
        x1B = *(const float4*)&g_xw[((size_t)NB + b1) * NH + j0];
    }

    for (int s = 0; s < T_SEQ; s++) {
        const int p = s & 1, q = p ^ 1;

        // ---- A-phase: local-half FMA, both chains (pre-wait overlap) ----
        unsigned long long aA0 = 0ull, aA1 = 0ull, aA2 = 0ull, aA3 = 0ull;
        unsigned long long aB0 = 0ull, aB1 = 0ull, aB2 = 0ull, aB3 = 0ull;
        {
            const ulonglong2* hA = (const ulonglong2*)&hbuf[0][p][PHYS16(lk)];
            const ulonglong2* hB = (const ulonglong2*)&hbuf[1][p][PHYS16(lk)];
#pragma unroll
            for (int i = 0; i < 4; i++) {
                ulonglong2 va = hA[i], vb = hB[i];
                aA0 = fma2(wl[0][2 * i], va.x, aA0);
                aA0 = fma2(wl[0][2 * i + 1], va.y, aA0);
                aA1 = fma2(wl[1][2 * i], va.x, aA1);
                aA1 = fma2(wl[1][2 * i + 1], va.y, aA1);
                aA2 = fma2(wl[2][2 * i], va.x, aA2);
                aA2 = fma2(wl[2][2 * i + 1], va.y, aA2);
                aA3 = fma2(wl[3][2 * i], va.x, aA3);
                aA3 = fma2(wl[3][2 * i + 1], va.y, aA3);
                aB0 = fma2(wl[0][2 * i], vb.x, aB0);
                aB0 = fma2(wl[0][2 * i + 1], vb.y, aB0);
                aB1 = fma2(wl[1][2 * i], vb.x, aB1);
                aB1 = fma2(wl[1][2 * i + 1], vb.y, aB1);
                aB2 = fma2(wl[2][2 * i], vb.x, aB2);
                aB2 = fma2(wl[2][2 * i + 1], vb.y, aB2);
                aB3 = fma2(wl[3][2 * i], vb.x, aB3);
                aB3 = fma2(wl[3][2 * i + 1], vb.y, aB3);
            }
        }

        // ---- wait for peer h(s) pushes (both chains; matches arrive s-1) --
        if (s) cluster_wait_();

        // ---- remote-half FMA, both chains ----
        {
            const ulonglong2* hA = (const ulonglong2*)&hbuf[0][p][PHYS16(rk)];
            const ulonglong2* hB = (const ulonglong2*)&hbuf[1][p][PHYS16(rk)];
#pragma unroll
            for (int i = 0; i < 4; i++) {
                ulonglong2 va = hA[i], vb = hB[i];
                aA0 = fma2(wr[0][2 * i], va.x, aA0);
                aA0 = fma2(wr[0][2 * i + 1], va.y, aA0);
                aA1 = fma2(wr[1][2 * i], va.x, aA1);
                aA1 = fma2(wr[1][2 * i + 1], va.y, aA1);
                aA2 = fma2(wr[2][2 * i], va.x, aA2);
                aA2 = fma2(wr[2][2 * i + 1], va.y, aA2);
                aA3 = fma2(wr[3][2 * i], va.x, aA3);
                aA3 = fma2(wr[3][2 * i + 1], va.y, aA3);
                aB0 = fma2(wr[0][2 * i], vb.x, aB0);
                aB0 = fma2(wr[0][2 * i + 1], vb.y, aB0);
                aB1 = fma2(wr[1][2 * i], vb.x, aB1);
                aB1 = fma2(wr[1][2 * i + 1], vb.y, aB1);
                aB2 = fma2(wr[2][2 * i], vb.x, aB2);
                aB2 = fma2(wr[2][2 * i + 1], vb.y, aB2);
                aB3 = fma2(wr[3][2 * i], vb.x, aB3);
                aB3 = fma2(wr[3][2 * i + 1], vb.y, aB3);
            }
        }
        float vA0 = f2sum(aA0), vA1 = f2sum(aA1), vA2 = f2sum(aA2), vA3 = f2sum(aA3);
        float vB0 = f2sum(aB0), vB1 = f2sum(aB1), vB2 = f2sum(aB2), vB3 = f2sum(aB3);
#pragma unroll
        for (int d = 4; d <= 16; d <<= 1) {       // butterfly over 8 k-parts
            vA0 += __shfl_xor_sync(0xffffffffu, vA0, d);
            vA1 += __shfl_xor_sync(0xffffffffu, vA1, d);
            vA2 += __shfl_xor_sync(0xffffffffu, vA2, d);
            vA3 += __shfl_xor_sync(0xffffffffu, vA3, d);
            vB0 += __shfl_xor_sync(0xffffffffu, vB0, d);
            vB1 += __shfl_xor_sync(0xffffffffu, vB1, d);
            vB2 += __shfl_xor_sync(0xffffffffu, vB2, d);
            vB3 += __shfl_xor_sync(0xffffffffu, vB3, d);
        }

        if (writer) {
            vA0 = tanh_fast(vA0 + xcA.x); vA1 = tanh_fast(vA1 + xcA.y);
            vA2 = tanh_fast(vA2 + xcA.z); vA3 = tanh_fast(vA3 + xcA.w);
            vB0 = tanh_fast(vB0 + xcB.x); vB1 = tanh_fast(vB1 + xcB.y);
            vB2 = tanh_fast(vB2 + xcB.z); vB3 = tanh_fast(vB3 + xcB.w);
            if (s + 1 < T_SEQ) {
                *(float4*)&hbuf[0][q][pj] = make_float4(vA0, vA1, vA2, vA3);
                *(float4*)&hbuf[1][q][pj] = make_float4(vB0, vB1, vB2, vB3);
                st_cluster_b64(rdA[q],     packf2(vA0, vA1));
                st_cluster_b64(rdA[q] + 8, packf2(vA2, vA3));
                st_cluster_b64(rdB[q],     packf2(vB0, vB1));
                st_cluster_b64(rdB[q] + 8, packf2(vB2, vB3));
            }
        }
        // ---- release my pushes; peers' wait(s+1) acquires them ----
        if (s + 1 < T_SEQ) cluster_arrive_();
        if (writer) {
            *(float4*)(out + ((size_t)s * NB + b0) * NH + j0) =
                make_float4(vA0, vA1, vA2, vA3);
            *(float4*)(out + ((size_t)s * NB + b1) * NH + j0) =
                make_float4(vB0, vB1, vB2, vB3);
            xcA = x1A; xcB = x1B;
            if (s + 2 < T_SEQ) {
                x1A = *(const float4*)&g_xw[((size_t)(s + 2) * NB + b0) * NH + j0];
                x1B = *(const float4*)&g_xw[((size_t)(s + 2) * NB + b1) * NH + j0];
            }
        }
        __syncthreads();   // local-half stores visible CTA-wide for next step
    }
    cluster_sync_();       // keep smem alive for in-flight peer stores
}

// =================================================================
extern "C" void kernel_launch(void* const* d_in, const int* in_sizes, int n_in,
                              void* d_out, int out_size) {
    const float* x    = (const float*)d_in[0];
    const float* w_ih = (const float*)d_in[1];
    const float* w_hh = (const float*)d_in[2];
    const float* b_ih = (const float*)d_in[3];
    const float* b_hh = (const float*)d_in[4];
    float* out = (float*)d_out;

    dim3 g1(1024, 2);
    xw_kernel<<<g1, 256>>>(x, w_ih, b_ih, b_hh);
    rnn_kernel<<<64, 256>>>(w_hh, out);
}

// round 8
// speedup vs baseline: 1.2890x; 1.2890x over previous
#include <cuda_runtime.h>
#include <cstdint>

#define T_SEQ 2048
#define NB    64
#define DIN   256
#define NH    256

// scratch: precomputed input projection xw[t][b][h]  (128 MB, static — no allocs)
__device__ float g_xw[(size_t)T_SEQ * NB * NH];

// padded h index: +4 words per 32-float window (stride 36) -> the 8 windows'
// i-th 16B subloads hit 32 DISTINCT banks => strictly conflict-free LDS.128
#define PHYS(k) ((k) + (((k) >> 5) << 2))
#define HPAD 288   // 256 + 8 windows * 4 pad

// ---------------- packed fp32x2 helpers (sm_100+) ----------------
__device__ __forceinline__ unsigned long long fma2(unsigned long long a,
                                                   unsigned long long b,
                                                   unsigned long long c) {
    unsigned long long d;
    asm("fma.rn.f32x2 %0, %1, %2, %3;" : "=l"(d) : "l"(a), "l"(b), "l"(c));
    return d;
}
__device__ __forceinline__ float f2sum(unsigned long long v) {
    float lo, hi;
    asm("mov.b64 {%0, %1}, %2;" : "=f"(lo), "=f"(hi) : "l"(v));
    return lo + hi;
}
__device__ __forceinline__ unsigned long long packf2(float lo, float hi) {
    unsigned long long r;
    asm("mov.b64 %0, {%1, %2};" : "=l"(r) : "f"(lo), "f"(hi));
    return r;
}
__device__ __forceinline__ uint32_t smem_u32(const void* p) {
    uint32_t a;
    asm("{ .reg .u64 t; cvta.to.shared.u64 t, %1; cvt.u32.u64 %0, t; }"
        : "=r"(a) : "l"(p));
    return a;
}
__device__ __forceinline__ uint32_t mapa_(uint32_t addr, int rank) {
    uint32_t r;
    asm("mapa.shared::cluster.u32 %0, %1, %2;" : "=r"(r) : "r"(addr), "r"(rank));
    return r;
}
__device__ __forceinline__ void cluster_sync_() {
    asm volatile("barrier.cluster.arrive.aligned;\n\t"
                 "barrier.cluster.wait.aligned;" ::: "memory");
}
__device__ __forceinline__ void cluster_arrive_() {
    asm volatile("barrier.cluster.arrive.aligned;" ::: "memory");
}
__device__ __forceinline__ void cluster_wait_() {
    asm volatile("barrier.cluster.wait.aligned;" ::: "memory");
}
__device__ __forceinline__ void st_cluster_b64(uint32_t addr, unsigned long long v) {
    asm volatile("st.shared::cluster.b64 [%0], %1;" :: "r"(addr), "l"(v) : "memory");
}
__device__ __forceinline__ float tanh_fast(float x) {
    float e = __expf(2.0f * x);
    return 1.0f - __fdividef(2.0f, e + 1.0f);
}

// =================================================================
// Kernel 1: input projection  (unchanged — proven)
// =================================================================
__global__ void __launch_bounds__(256, 1)
xw_kernel(const float* __restrict__ x,
          const float* __restrict__ w_ih,
          const float* __restrict__ b_ih,
          const float* __restrict__ b_hh) {
    __shared__ __align__(16) float xs[8][256];
    __shared__ float pbuf[8 * 512];

    const int tid  = threadIdx.x;
    const int w    = tid >> 5;
    const int lane = tid & 31;
    const int kg   = w >> 1;
    const int og   = ((w & 1) << 5) | lane;
    const int half = blockIdx.y;
    const int rowbase0 = blockIdx.x * 128;

    unsigned long long wa[32], wb[32];
    {
        const int j0 = half * 128 + og, j1 = j0 + 64;
        const unsigned long long* p0 =
            (const unsigned long long*)(w_ih + (size_t)j0 * DIN + kg * 64);
        const unsigned long long* p1 =
            (const unsigned long long*)(w_ih + (size_t)j1 * DIN + kg * 64);
#pragma unroll
        for (int i = 0; i < 32; i++) { wa[i] = p0[i]; wb[i] = p1[i]; }
    }
    float bias = 0.f;
    if (tid < 128) bias = b_ih[half * 128 + tid] + b_hh[half * 128 + tid];

    const float4* xg = (const float4*)x;
    {
        int q = tid, r = q >> 6, c4 = q & 63;
        ((float4*)xs)[q]       = xg[(size_t)(rowbase0 + r) * 64 + c4];
        ((float4*)xs)[q + 256] = xg[(size_t)(rowbase0 + 4 + r) * 64 + c4];
    }
    __syncthreads();

    for (int it = 0; it < 16; it++) {
        const int rowbase = rowbase0 + it * 8;
        float4 n0, n1;
        if (it < 15) {
            int q = tid, r = q >> 6, c4 = q & 63;
            int nrb = rowbase + 8;
            n0 = xg[(size_t)(nrb + r) * 64 + c4];
            n1 = xg[(size_t)(nrb + 4 + r) * 64 + c4];
        }
        unsigned long long acc[8][2];
#pragma unroll
        for (int r = 0; r < 8; r++) { acc[r][0] = 0ull; acc[r][1] = 0ull; }
#pragma unroll
        for (int r = 0; r < 8; r++) {
            const ulonglong2* xp = (const ulonglong2*)&xs[r][kg * 64];
#pragma unroll
            for (int i = 0; i < 16; i++) {
                ulonglong2 hv = xp[i];
                acc[r][0] = fma2(wa[2 * i],     hv.x, acc[r][0]);
                acc[r][0] = fma2(wa[2 * i + 1], hv.y, acc[r][0]);
                acc[r][1] = fma2(wb[2 * i],     hv.x, acc[r][1]);
                acc[r][1] = fma2(wb[2 * i + 1], hv.y, acc[r][1]);
            }
        }
#pragma unroll
        for (int r = 0; r < 8; r++) {
            pbuf[r * 512 + kg * 128 + og]      = f2sum(acc[r][0]);
            pbuf[r * 512 + kg * 128 + og + 64] = f2sum(acc[r][1]);
        }
        __syncthreads();
        if (it < 15) {
            int q = tid;
            ((float4*)xs)[q]       = n0;
            ((float4*)xs)[q + 256] = n1;
        }
        if (tid < 128) {
#pragma unroll
            for (int r = 0; r < 8; r++) {
                float s = pbuf[r * 512 + tid] + pbuf[r * 512 + 128 + tid] +
                          pbuf[r * 512 + 256 + tid] + pbuf[r * 512 + 384 + tid] + bias;
                g_xw[(size_t)(rowbase + r) * NH + half * 128 + tid] = s;
            }
        }
        __syncthreads();
    }
}

// =================================================================
// Kernel 2: recurrence v8 — ONE barrier pair per step, nothing else.
//   64 clusters x 2 CTAs x 256 thr. CTA c owns output cols [c*128,+128).
//   Lane (w,l): cg=l&3 -> 4 cols; kp=l>>2 -> one contiguous 32-k window.
//   Step: wait(gen s-1) -> full-k FMA -> 3x shfl reduce -> tanh
//   -> STS local h + st.shared::cluster push -> arrive(gen s)
//   -> [off-chain STG + xw prefetch]. No __syncthreads in the loop.
//   All h stores precede arrive, so the aligned cluster barrier's
//   release/acquire orders them cluster-wide (incl. own CTA).
// =================================================================
__global__ void __launch_bounds__(256, 1) __cluster_dims__(2, 1, 1)
rnn_kernel(const float* __restrict__ w_hh, float* __restrict__ out) {
    __shared__ __align__(16) float hbuf[2][HPAD];   // full h, padded, 2-buf

    const int tid  = threadIdx.x;
    const int w    = tid >> 5, l = tid & 31;
    const int cg   = l & 3,  kp = l >> 2;
    const int b    = blockIdx.x >> 1;
    const int c    = blockIdx.x & 1;
    const int peer = c ^ 1;
    const int j0   = c * 128 + w * 16 + cg * 4;    // 4 output cols (global)
    const int k0   = kp * 32;                      // contiguous 32-k window
    const bool writer = (kp == 0);

    // register-resident weights: rows j0..j0+3, k in [k0, k0+32)
    unsigned long long wv[4][16];
#pragma unroll
    for (int cc = 0; cc < 4; cc++) {
        const unsigned long long* row =
            (const unsigned long long*)(w_hh + (size_t)(j0 + cc) * NH + k0);
#pragma unroll
        for (int i = 0; i < 16; i++) wv[cc][i] = row[i];
    }

    for (int i = tid; i < 2 * HPAD; i += 256) ((float*)hbuf)[i] = 0.f;  // h0=0

    const int pj = PHYS(j0);                       // writer store offset
    const uint32_t rdst[2] = { mapa_(smem_u32(&hbuf[0][pj]), peer),
                               mapa_(smem_u32(&hbuf[1][pj]), peer) };

    cluster_sync_();                               // zeros visible cluster-wide

    float4 xc, x1;
    if (writer) {
        xc = *(const float4*)&g_xw[(size_t)b * NH + j0];
        x1 = *(const float4*)&g_xw[((size_t)NB + b) * NH + j0];
    }

    for (int s = 0; s < T_SEQ; s++) {
        const int p = s & 1, q = p ^ 1;

        // ---- h(s) fully visible after this (matches arrive of step s-1) ---
        if (s) cluster_wait_();

        // ---- GEMV slice: 4 cols x 32 k (8 LDS.128 conflict-free, 64 fma2) -
        const ulonglong2* hp = (const ulonglong2*)&hbuf[p][PHYS(k0)];
        unsigned long long a0 = 0ull, a1 = 0ull, a2 = 0ull, a3 = 0ull;
#pragma unroll
        for (int i = 0; i < 8; i++) {
            ulonglong2 hv = hp[i];
            a0 = fma2(wv[0][2 * i], hv.x, a0);
            a0 = fma2(wv[0][2 * i + 1], hv.y, a0);
            a1 = fma2(wv[1][2 * i], hv.x, a1);
            a1 = fma2(wv[1][2 * i + 1], hv.y, a1);
            a2 = fma2(wv[2][2 * i], hv.x, a2);
            a2 = fma2(wv[2][2 * i + 1], hv.y, a2);
            a3 = fma2(wv[3][2 * i], hv.x, a3);
            a3 = fma2(wv[3][2 * i + 1], hv.y, a3);
        }
        float v0 = f2sum(a0), v1 = f2sum(a1), v2 = f2sum(a2), v3 = f2sum(a3);
#pragma unroll
        for (int d = 4; d <= 16; d <<= 1) {        // butterfly over 8 k-parts
            v0 += __shfl_xor_sync(0xffffffffu, v0, d);
            v1 += __shfl_xor_sync(0xffffffffu, v1, d);
            v2 += __shfl_xor_sync(0xffffffffu, v2, d);
            v3 += __shfl_xor_sync(0xffffffffu, v3, d);
        }

        if (writer) {
            v0 = tanh_fast(v0 + xc.x);
            v1 = tanh_fast(v1 + xc.y);
            v2 = tanh_fast(v2 + xc.z);
            v3 = tanh_fast(v3 + xc.w);
            if (s + 1 < T_SEQ) {
                *(float4*)&hbuf[q][pj] = make_float4(v0, v1, v2, v3);  // local
                st_cluster_b64(rdst[q],     packf2(v0, v1));           // remote
                st_cluster_b64(rdst[q] + 8, packf2(v2, v3));
            }
        }
        // ---- release all h(s+1) stores; peers' wait(s+1) acquires them ----
        if (s + 1 < T_SEQ) cluster_arrive_();

        // ---- off-critical-path tail ----
        if (writer) {
            *(float4*)(out + ((size_t)s * NB + b) * NH + j0) =
                make_float4(v0, v1, v2, v3);
            xc = x1;
            if (s + 2 < T_SEQ)
                x1 = *(const float4*)&g_xw[((size_t)(s + 2) * NB + b) * NH + j0];
        }
    }
    cluster_sync_();   // keep smem alive for in-flight peer stores
}

// =================================================================
extern "C" void kernel_launch(void* const* d_in, const int* in_sizes, int n_in,
                              void* d_out, int out_size) {
    const float* x    = (const float*)d_in[0];
    const float* w_ih = (const float*)d_in[1];
    const float* w_hh = (const float*)d_in[2];
    const float* b_ih = (const float*)d_in[3];
    const float* b_hh = (const float*)d_in[4];
    float* out = (float*)d_out;

    dim3 g1(1024, 2);
    xw_kernel<<<g1, 256>>>(x, w_ih, b_ih, b_hh);
    rnn_kernel<<<128, 256>>>(w_hh, out);
}

// round 9
// speedup vs baseline: 1.7241x; 1.3375x over previous
#include <cuda_runtime.h>
#include <cstdint>

#define T_SEQ 2048
#define NB    64
#define DIN   256
#define NH    256

#define NAN_PAT 0x7FC00000u

// scratch: precomputed input projection xw[t][b][h]  (128 MB, static — no allocs)
__device__ float g_xw[(size_t)T_SEQ * NB * NH];

// padded h index: +4 words per 32-float window (stride 36) -> conflict-free LDS.128
#define PHYS(k) ((k) + (((k) >> 5) << 2))
#define HPAD 288   // 256 + 8 windows * 4 pad

// ---------------- packed fp32x2 helpers (sm_100+) ----------------
__device__ __forceinline__ unsigned long long fma2(unsigned long long a,
                                                   unsigned long long b,
                                                   unsigned long long c) {
    unsigned long long d;
    asm("fma.rn.f32x2 %0, %1, %2, %3;" : "=l"(d) : "l"(a), "l"(b), "l"(c));
    return d;
}
__device__ __forceinline__ float f2sum(unsigned long long v) {
    float lo, hi;
    asm("mov.b64 {%0, %1}, %2;" : "=f"(lo), "=f"(hi) : "l"(v));
    return lo + hi;
}
__device__ __forceinline__ unsigned long long packf2(float lo, float hi) {
    unsigned long long r;
    asm("mov.b64 %0, {%1, %2};" : "=l"(r) : "f"(lo), "f"(hi));
    return r;
}
__device__ __forceinline__ uint32_t smem_u32(const void* p) {
    uint32_t a;
    asm("{ .reg .u64 t; cvta.to.shared.u64 t, %1; cvt.u32.u64 %0, t; }"
        : "=r"(a) : "l"(p));
    return a;
}
__device__ __forceinline__ uint32_t mapa_(uint32_t addr, int rank) {
    uint32_t r;
    asm("mapa.shared::cluster.u32 %0, %1, %2;" : "=r"(r) : "r"(addr), "r"(rank));
    return r;
}
__device__ __forceinline__ void cluster_sync_() {
    asm volatile("barrier.cluster.arrive.aligned;\n\t"
                 "barrier.cluster.wait.aligned;" ::: "memory");
}
__device__ __forceinline__ void st_cluster_b64(uint32_t addr, unsigned long long v) {
    asm volatile("st.shared::cluster.b64 [%0], %1;" :: "r"(addr), "l"(v) : "memory");
}
// volatile 16B smem load (poll + data in one)
__device__ __forceinline__ void ldv2(uint32_t a, unsigned long long& x,
                                     unsigned long long& y) {
    asm volatile("ld.volatile.shared.v2.u64 {%0, %1}, [%2];"
                 : "=l"(x), "=l"(y) : "r"(a) : "memory");
}
__device__ __forceinline__ void stv2(uint32_t a, unsigned long long x,
                                     unsigned long long y) {
    asm volatile("st.volatile.shared.v2.u64 [%0], {%1, %2};"
                 :: "r"(a), "l"(x), "l"(y) : "memory");
}
__device__ __forceinline__ void st32(uint32_t a, uint32_t v) {
    asm volatile("st.volatile.shared.u32 [%0], %1;" :: "r"(a), "r"(v) : "memory");
}
__device__ __forceinline__ float tanh_fast(float x) {
    float e = __expf(2.0f * x);
    return 1.0f - __fdividef(2.0f, e + 1.0f);
}

// =================================================================
// Kernel 1: input projection  (unchanged — proven)
// =================================================================
__global__ void __launch_bounds__(256, 1)
xw_kernel(const float* __restrict__ x,
          const float* __restrict__ w_ih,
          const float* __restrict__ b_ih,
          const float* __restrict__ b_hh) {
    __shared__ __align__(16) float xs[8][256];
    __shared__ float pbuf[8 * 512];

    const int tid  = threadIdx.x;
    const int w    = tid >> 5;
    const int lane = tid & 31;
    const int kg   = w >> 1;
    const int og   = ((w & 1) << 5) | lane;
    const int half = blockIdx.y;
    const int rowbase0 = blockIdx.x * 128;

    unsigned long long wa[32], wb[32];
    {
        const int j0 = half * 128 + og, j1 = j0 + 64;
        const unsigned long long* p0 =
            (const unsigned long long*)(w_ih + (size_t)j0 * DIN + kg * 64);
        const unsigned long long* p1 =
            (const unsigned long long*)(w_ih + (size_t)j1 * DIN + kg * 64);
#pragma unroll
        for (int i = 0; i < 32; i++) { wa[i] = p0[i]; wb[i] = p1[i]; }
    }
    float bias = 0.f;
    if (tid < 128) bias = b_ih[half * 128 + tid] + b_hh[half * 128 + tid];

    const float4* xg = (const float4*)x;
    {
        int q = tid, r = q >> 6, c4 = q & 63;
        ((float4*)xs)[q]       = xg[(size_t)(rowbase0 + r) * 64 + c4];
        ((float4*)xs)[q + 256] = xg[(size_t)(rowbase0 + 4 + r) * 64 + c4];
    }
    __syncthreads();

    for (int it = 0; it < 16; it++) {
        const int rowbase = rowbase0 + it * 8;
        float4 n0, n1;
        if (it < 15) {
            int q = tid, r = q >> 6, c4 = q & 63;
            int nrb = rowbase + 8;
            n0 = xg[(size_t)(nrb + r) * 64 + c4];
            n1 = xg[(size_t)(nrb + 4 + r) * 64 + c4];
        }
        unsigned long long acc[8][2];
#pragma unroll
        for (int r = 0; r < 8; r++) { acc[r][0] = 0ull; acc[r][1] = 0ull; }
#pragma unroll
        for (int r = 0; r < 8; r++) {
            const ulonglong2* xp = (const ulonglong2*)&xs[r][kg * 64];
#pragma unroll
            for (int i = 0; i < 16; i++) {
                ulonglong2 hv = xp[i];
                acc[r][0] = fma2(wa[2 * i],     hv.x, acc[r][0]);
                acc[r][0] = fma2(wa[2 * i + 1], hv.y, acc[r][0]);
                acc[r][1] = fma2(wb[2 * i],     hv.x, acc[r][1]);
                acc[r][1] = fma2(wb[2 * i + 1], hv.y, acc[r][1]);
            }
        }
#pragma unroll
        for (int r = 0; r < 8; r++) {
            pbuf[r * 512 + kg * 128 + og]      = f2sum(acc[r][0]);
            pbuf[r * 512 + kg * 128 + og + 64] = f2sum(acc[r][1]);
        }
        __syncthreads();
        if (it < 15) {
            int q = tid;
            ((float4*)xs)[q]       = n0;
            ((float4*)xs)[q + 256] = n1;
        }
        if (tid < 128) {
#pragma unroll
            for (int r = 0; r < 8; r++) {
                float s = pbuf[r * 512 + tid] + pbuf[r * 512 + 128 + tid] +
                          pbuf[r * 512 + 256 + tid] + pbuf[r * 512 + 384 + tid] + bias;
                g_xw[(size_t)(rowbase + r) * NH + half * 128 + tid] = s;
            }
        }
        __syncthreads();
    }
}

// =================================================================
// Kernel 2: recurrence v9 — barrier-free sentinel dataflow.
//   64 clusters x 2 CTAs x 256 thr. CTA c owns cols [c*128,+128).
//   h in 4 rotating slots; a 16B chunk is "present" iff its two head
//   words != NaN sentinel (tanh output in (-1,1) can never be NaN).
//   Step s: poll slot[s%4] (loads ARE the data) -> FMA -> reset heads of
//   slot[(s+2)%4] (warps 0-3, BEFORE their pushes) -> reduce -> tanh ->
//   push h(s+1) into slot[(s+1)%4] (local v2.u64 + remote 2x cluster b64)
//   -> [off-chain STG + xw prefetch]. No barriers/fences in the loop.
// =================================================================
__global__ void __launch_bounds__(256, 1) __cluster_dims__(2, 1, 1)
rnn_kernel(const float* __restrict__ w_hh, float* __restrict__ out) {
    __shared__ __align__(16) float hbuf[4][HPAD];   // 4 rotating slots

    const int tid  = threadIdx.x;
    const int w    = tid >> 5, l = tid & 31;
    const int cg   = l & 3,  kp = l >> 2;
    const int b    = blockIdx.x >> 1;
    const int c    = blockIdx.x & 1;
    const int peer = c ^ 1;
    const int j0   = c * 128 + w * 16 + cg * 4;    // 4 output cols (global)
    const int k0   = kp * 32;                      // contiguous 32-k window
    const bool writer = (kp == 0);

    // register-resident weights: rows j0..j0+3, k in [k0, k0+32)
    unsigned long long wv[4][16];
#pragma unroll
    for (int cc = 0; cc < 4; cc++) {
        const unsigned long long* row =
            (const unsigned long long*)(w_hh + (size_t)(j0 + cc) * NH + k0);
#pragma unroll
        for (int i = 0; i < 16; i++) wv[cc][i] = row[i];
    }

    // slot 0 = h0 = 0 (valid); slots 1..3 = sentinel
    for (int i = tid; i < HPAD; i += 256) hbuf[0][i] = 0.f;
    for (int i = HPAD + tid; i < 4 * HPAD; i += 256)
        ((uint32_t*)hbuf)[i] = NAN_PAT;

    // per-lane addresses
    uint32_t wbase[4];                             // my k-window, per slot
#pragma unroll
    for (int s4 = 0; s4 < 4; s4++) wbase[s4] = smem_u32(&hbuf[s4][PHYS(k0)]);

    const int pj = PHYS(j0);
    uint32_t lcw[4], rcw[4];                       // writer chunk, local/remote
#pragma unroll
    for (int s4 = 0; s4 < 4; s4++) {
        lcw[s4] = smem_u32(&hbuf[s4][pj]);
        rcw[s4] = mapa_(lcw[s4], peer);
    }
    // reset duty: tid<128 resets head word tid of each slot
    uint32_t rst[4];
    {
        int chunk = tid >> 1, half = tid & 1;
        int off = 36 * (chunk >> 3) + 4 * (chunk & 7) + half * 2;
#pragma unroll
        for (int s4 = 0; s4 < 4; s4++) rst[s4] = smem_u32(&hbuf[s4][off]);
    }

    cluster_sync_();   // init visible cluster-wide before any remote push

    float4 xc, x1;
    if (writer) {
        xc = *(const float4*)&g_xw[(size_t)b * NH + j0];
        x1 = *(const float4*)&g_xw[((size_t)NB + b) * NH + j0];
    }

    for (int s = 0; s < T_SEQ; s++) {
        const int sp = s & 3, sq = (s + 1) & 3, sr = (s + 2) & 3;

        // ---- poll h(s): loads are the data; chunk present iff heads!=NaN --
        unsigned long long hx[8], hy[8];
        const uint32_t wb = wbase[sp];
        bool ok;
        do {
            ok = true;
#pragma unroll
            for (int i = 0; i < 8; i++) {
                ldv2(wb + 16u * i, hx[i], hy[i]);
                ok &= ((uint32_t)hx[i] != NAN_PAT) & ((uint32_t)hy[i] != NAN_PAT);
            }
        } while (!__all_sync(0xffffffffu, ok));

        // ---- reset heads of slot sr (h(s-2) slot -> future h(s+2)).
        //      Emitted BEFORE this warp's pushes (program order gates peer).
        if (tid < 128) st32(rst[sr], NAN_PAT);

        // ---- GEMV slice: 4 cols x 32 k (64 fma2) ----
        unsigned long long a0 = 0ull, a1 = 0ull, a2 = 0ull, a3 = 0ull;
#pragma unroll
        for (int i = 0; i < 8; i++) {
            a0 = fma2(wv[0][2 * i], hx[i], a0);
            a0 = fma2(wv[0][2 * i + 1], hy[i], a0);
            a1 = fma2(wv[1][2 * i], hx[i], a1);
            a1 = fma2(wv[1][2 * i + 1], hy[i], a1);
            a2 = fma2(wv[2][2 * i], hx[i], a2);
            a2 = fma2(wv[2][2 * i + 1], hy[i], a2);
            a3 = fma2(wv[3][2 * i], hx[i], a3);
            a3 = fma2(wv[3][2 * i + 1], hy[i], a3);
        }
        float v0 = f2sum(a0), v1 = f2sum(a1), v2 = f2sum(a2), v3 = f2sum(a3);
#pragma unroll
        for (int d = 4; d <= 16; d <<= 1) {        // butterfly over 8 k-parts
            v0 += __shfl_xor_sync(0xffffffffu, v0, d);
            v1 += __shfl_xor_sync(0xffffffffu, v1, d);
            v2 += __shfl_xor_sync(0xffffffffu, v2, d);
            v3 += __shfl_xor_sync(0xffffffffu, v3, d);
        }

        if (writer) {
            v0 = tanh_fast(v0 + xc.x);
            v1 = tanh_fast(v1 + xc.y);
            v2 = tanh_fast(v2 + xc.z);
            v3 = tanh_fast(v3 + xc.w);
            if (s + 1 < T_SEQ) {
                unsigned long long p01 = packf2(v0, v1), p23 = packf2(v2, v3);
                stv2(lcw[sq], p01, p23);           // local chunk (8B-atomic halves)
                st_cluster_b64(rcw[sq],     p01);  // remote copy
                st_cluster_b64(rcw[sq] + 8, p23);
            }
            // off-critical-path tail
            *(float4*)(out + ((size_t)s * NB + b) * NH + j0) =
                make_float4(v0, v1, v2, v3);
            xc = x1;
            if (s + 2 < T_SEQ)
                x1 = *(const float4*)&g_xw[((size_t)(s + 2) * NB + b) * NH + j0];
        }
    }
    cluster_sync_();   // keep smem alive for in-flight peer stores
}

// =================================================================
extern "C" void kernel_launch(void* const* d_in, const int* in_sizes, int n_in,
                              void* d_out, int out_size) {
    const float* x    = (const float*)d_in[0];
    const float* w_ih = (const float*)d_in[1];
    const float* w_hh = (const float*)d_in[2];
    const float* b_ih = (const float*)d_in[3];
    const float* b_hh = (const float*)d_in[4];
    float* out = (float*)d_out;

    dim3 g1(1024, 2);
    xw_kernel<<<g1, 256>>>(x, w_ih, b_ih, b_hh);
    rnn_kernel<<<128, 256>>>(w_hh, out);
}